// round 5
// baseline (speedup 1.0000x reference)
#include <cuda_runtime.h>
#include <cuda_bf16.h>

// CTC forward (keras ctc_batch_cost), scaled linear domain, two-phase:
//   Phase A: gather/pack P[b,t,class]+eps for the 49 needed classes into a
//            compact G[b][t][64] buffer (massively parallel, bandwidth-bound).
//   Phase B: 97-state scan, 1 warp/batch, reading compact coalesced G.
// B=128, T=512, C=1024 (blank=C-1), L=48, S=97.
//
// G slot layout per (b,t): slot j in [0,48) = p(label j)+eps; slot 62 = p(blank)+eps;
// slots 48..61 and 63 = 0.0f (so lanes >= 24 of the scan self-mask via *0).
//
// y_true dtype (int32 vs int64) auto-detected: int64 labels viewed as int32
// have all odd 32-bit words == 0.

#define BB 128
#define TT 512
#define CC 1024
#define LL 48
#define SS 97
#define EPSV 1e-7f
#define GW 64          // packed row width
#define BLANK_SLOT 62
#define RD 16          // scan prefetch ring depth

__device__ int g_lab_stride;                     // 1: int32, 2: int64
__device__ float g_G[(size_t)BB * TT * GW];      // 16.8 MB packed probs

__global__ void detect_dtype_kernel(const int* __restrict__ yt32) {
    __shared__ int any_odd;
    if (threadIdx.x == 0) any_odd = 0;
    __syncthreads();
    int local = 0;
    for (int i = 1 + 2 * threadIdx.x; i < BB * LL; i += 2 * blockDim.x)
        local |= yt32[i];
    if (local) atomicOr(&any_odd, 1);
    __syncthreads();
    if (threadIdx.x == 0) g_lab_stride = any_odd ? 1 : 2;
}

__device__ __forceinline__ int load_label(const int* yt, int idx, int stride) {
    int v = yt[idx * stride];
    return (v < 0) ? 0 : (v > CC - 1 ? CC - 1 : v);  // crash insurance
}

// Phase A: grid (TT/4, BB), block 256. tid -> (t_local, slot).
__global__ __launch_bounds__(256)
void ctc_gather_kernel(const float* __restrict__ yp,
                       const int* __restrict__ yt32) {
    const int b = blockIdx.y;
    const int t = blockIdx.x * 4 + (threadIdx.x >> 6);
    const int s = threadIdx.x & 63;
    const int stride = g_lab_stride;
    const int* __restrict__ Yt = yt32 + (size_t)b * LL * stride;
    const float* __restrict__ Pt = yp + ((size_t)b * TT + t) * CC;

    float v = 0.0f;
    if (s < LL) {
        v = Pt[load_label(Yt, s, stride)] + EPSV;
    } else if (s == BLANK_SLOT) {
        v = Pt[CC - 1] + EPSV;
    }
    g_G[((size_t)b * TT + t) * GW + s] = v;
}

// Phase B: 1 warp per batch. Lane l owns states 4l..4l+3.
//   new[s] = (a[s] + a[s-1] + skip[s]*a[s-2]) * g[t, slot(s)]
// Only cross-lane term: old a[4l-1] via one shfl. Exact power-of-2 rescale
// every 4 steps via redux-max (positive floats compare as uints).
__global__ __launch_bounds__(32, 1)
void ctc_scan_kernel(const int* __restrict__ yt32, float* __restrict__ out) {
    const int b = blockIdx.x;
    const int lane = threadIdx.x;
    const unsigned FULL = 0xffffffffu;
    const int stride = g_lab_stride;
    const int* __restrict__ Yt = yt32 + (size_t)b * LL * stride;
    const float* __restrict__ G = g_G + (size_t)b * TT * GW;

    // skip flags for odd states 4l+1 (label 2l) and 4l+3 (label 2l+1)
    const int i0 = 2 * lane, i1 = 2 * lane + 1;
    const int blank = CC - 1;
    const int lab0 = (i0 < LL) ? load_label(Yt, i0, stride) : blank;
    const int lab1 = (i1 < LL) ? load_label(Yt, i1, stride) : blank;
    const int labm1 = (i0 >= 1 && i0 <= LL) ? load_label(Yt, i0 - 1, stride) : -1;
    const float sk1 = (lab0 != labm1) ? 1.0f : 0.0f;
    const float sk3 = (lab1 != lab0) ? 1.0f : 0.0f;

    // t=0 init: state0 = blank, state1 = label0 (lane 0 only)
    float a0 = 0.0f, a1 = 0.0f, a2 = 0.0f, a3 = 0.0f;
    if (lane == 0) { a0 = G[BLANK_SLOT]; a1 = G[0]; }

    // prefetch ring: float2 (slots 2l,2l+1) + blank scalar, t = 1..RD
    float2 v01[RD];
    float vb[RD];
#pragma unroll
    for (int i = 0; i < RD; i++) {
        const float* Gt = G + (size_t)(1 + i) * GW;
        v01[i] = *(const float2*)(Gt + 2 * lane);
        vb[i] = Gt[BLANK_SLOT];
    }

    int eTot = 0;

    for (int outer = 0; outer < TT / RD; outer++) {
#pragma unroll
        for (int i = 0; i < RD; i++) {
            const int t = 1 + outer * RD + i;
            if (t < TT) {
                const float pb = vb[i];
                const float p0 = v01[i].x;
                const float p1 = v01[i].y;

                float am1 = __shfl_up_sync(FULL, a3, 1);
                if (lane == 0) am1 = 0.0f;

                const float n0 = (a0 + am1) * pb;
                const float n1 = fmaf(sk1, am1, a0 + a1) * p0;
                const float n2 = (a1 + a2) * pb;
                const float n3 = fmaf(sk3, a1, a2 + a3) * p1;
                a0 = n0; a1 = n1; a2 = n2; a3 = n3;

                const int tp = t + RD;
                if (tp < TT) {
                    const float* Gt = G + (size_t)tp * GW;
                    v01[i] = *(const float2*)(Gt + 2 * lane);
                    vb[i] = Gt[BLANK_SLOT];
                }

                if ((i & 3) == 3) {
                    const float m = fmaxf(fmaxf(a0, a1), fmaxf(a2, a3));
                    const unsigned mu =
                        __reduce_max_sync(FULL, __float_as_uint(m));
                    if (mu) {
                        const int e = (int)(mu >> 23) - 127;
                        const float sc = __int_as_float((127 - e) << 23);
                        a0 *= sc; a1 *= sc; a2 *= sc; a3 *= sc;
                        eTot += e;
                    }
                }
            }
        }
    }

    // loss = -( log(alpha[96] + alpha[95]) + eTot*ln2 )
    const float aS1 = __shfl_sync(FULL, a0, 24);  // state 96: lane 24 slot 0
    const float aS2 = __shfl_sync(FULL, a3, 23);  // state 95: lane 23 slot 3
    if (lane == 0)
        out[b] = -(logf(aS1 + aS2) + (float)eTot * 0.6931471805599453f);
}

extern "C" void kernel_launch(void* const* d_in, const int* in_sizes, int n_in,
                              void* d_out, int out_size) {
    const float* yp;
    const int* yt32;
    if (in_sizes[0] == BB * LL) {
        yt32 = (const int*)d_in[0];
        yp = (const float*)d_in[1];
    } else {
        yp = (const float*)d_in[0];
        yt32 = (const int*)d_in[1];
    }
    detect_dtype_kernel<<<1, 256>>>(yt32);
    ctc_gather_kernel<<<dim3(TT / 4, BB), 256>>>(yp, yt32);
    ctc_scan_kernel<<<BB, 32>>>(yt32, (float*)d_out);
}